// round 1
// baseline (speedup 1.0000x reference)
#include <cuda_runtime.h>
#include <cuda_bf16.h>
#include <cstdint>

// ---------------- problem constants ----------------
#define BB   4
#define NQ_  1024
#define NK_  1024
#define DD   1024
#define HH   16
#define DH_  64
#define DFF_ 4096
#define M_ROWS (BB * NQ_)   // 4096
#define SCALE_ (1.0f / 32.0f)
#define LN_EPS 1e-5f

// ---------------- scratch (static device memory; no allocs allowed) ----------
__device__ float g_q[M_ROWS * DD];
__device__ float g_k[M_ROWS * DD];
__device__ float g_v[M_ROWS * DD];
__device__ float g_o[M_ROWS * DD];
__device__ float g_t[M_ROWS * DD];
__device__ float g_x[M_ROWS * DD];
__device__ float g_h[(size_t)M_ROWS * DFF_];

// ---------------- SGEMM: C[M,N] = A[M,K] @ B[K,N] + bias (opt ReLU) ---------
// 128x128 tile, BK=8, 256 threads, 8x8 per thread.
template <int RELU>
__global__ void __launch_bounds__(256) sgemm_kernel(
    const float* __restrict__ A, const float* __restrict__ B,
    const float* __restrict__ bias, float* __restrict__ C,
    int M, int N, int K)
{
    __shared__ float As[8][128];
    __shared__ float Bs[8][128];

    const int tid = threadIdx.x;
    const int row0 = blockIdx.y * 128;
    const int col0 = blockIdx.x * 128;
    const int tr = tid >> 4;        // 0..15
    const int tc = tid & 15;        // 0..15

    // global load mapping
    const int arow = tid >> 1;            // 0..127
    const int acol = (tid & 1) * 4;       // 0 or 4
    const int brow = tid >> 5;            // 0..7
    const int bcol = (tid & 31) * 4;      // 0..124

    const float* Ag = A + (size_t)(row0 + arow) * K + acol;
    const float* Bg = B + (size_t)brow * N + col0 + bcol;

    float acc[8][8];
    #pragma unroll
    for (int i = 0; i < 8; i++)
        #pragma unroll
        for (int j = 0; j < 8; j++) acc[i][j] = 0.0f;

    for (int k0 = 0; k0 < K; k0 += 8) {
        float4 a4 = *(const float4*)(Ag + k0);
        float4 b4 = *(const float4*)(Bg + (size_t)k0 * N);
        As[acol + 0][arow] = a4.x;
        As[acol + 1][arow] = a4.y;
        As[acol + 2][arow] = a4.z;
        As[acol + 3][arow] = a4.w;
        *(float4*)&Bs[brow][bcol] = b4;
        __syncthreads();

        #pragma unroll
        for (int kk = 0; kk < 8; kk++) {
            float ra[8], rb[8];
            #pragma unroll
            for (int i = 0; i < 8; i++) ra[i] = As[kk][tr * 8 + i];
            #pragma unroll
            for (int j = 0; j < 8; j++) rb[j] = Bs[kk][tc * 8 + j];
            #pragma unroll
            for (int i = 0; i < 8; i++)
                #pragma unroll
                for (int j = 0; j < 8; j++)
                    acc[i][j] = fmaf(ra[i], rb[j], acc[i][j]);
        }
        __syncthreads();
    }

    #pragma unroll
    for (int i = 0; i < 8; i++) {
        const size_t r = row0 + tr * 8 + i;
        #pragma unroll
        for (int j = 0; j < 8; j += 4) {
            const int c = col0 + tc * 8 + j;
            float4 b = *(const float4*)&bias[c];
            float4 v;
            v.x = acc[i][j + 0] + b.x;
            v.y = acc[i][j + 1] + b.y;
            v.z = acc[i][j + 2] + b.z;
            v.w = acc[i][j + 3] + b.w;
            if (RELU) {
                v.x = fmaxf(v.x, 0.f); v.y = fmaxf(v.y, 0.f);
                v.z = fmaxf(v.z, 0.f); v.w = fmaxf(v.w, 0.f);
            }
            *(float4*)&C[r * N + c] = v;
        }
    }
}

// ---------------- flash attention -------------------------------------------
// grid: (NQ/64, H, B), 256 threads. Q tile 64 rows, KV tiles of 32 rows.
// Thread (ty,tx): ty=tid/16, tx=tid%16. Owns S rows ty*4..+3, S cols tx*2..+1,
// O cols tx*4..+3.
__global__ void __launch_bounds__(256) attn_kernel(
    const float* __restrict__ q, const float* __restrict__ k,
    const float* __restrict__ v, float* __restrict__ o)
{
    __shared__ float Qs[64 * 65];   // transposed: Qs[d*65 + i]
    __shared__ float Ks[64 * 33];   // transposed: Ks[d*33 + j]
    __shared__ float Vs[32 * 68];   // row-major:  Vs[j*68 + d]
    __shared__ float Ps[64 * 36];   // row-major:  Ps[i*36 + j]

    const int tid = threadIdx.x;
    const int ty = tid >> 4;
    const int tx = tid & 15;
    const int q0 = blockIdx.x * 64;
    const int h  = blockIdx.y;
    const int b  = blockIdx.z;

    const size_t rowbase = (size_t)b * NQ_;
    const int colbase = h * DH_;

    // load Q tile (transposed into smem)
    #pragma unroll
    for (int it = 0; it < 4; it++) {
        const int r = ty + 16 * it;
        float4 t = *(const float4*)&q[(rowbase + q0 + r) * DD + colbase + tx * 4];
        Qs[(tx * 4 + 0) * 65 + r] = t.x;
        Qs[(tx * 4 + 1) * 65 + r] = t.y;
        Qs[(tx * 4 + 2) * 65 + r] = t.z;
        Qs[(tx * 4 + 3) * 65 + r] = t.w;
    }

    float m_i[4], l_i[4], Oa[4][4];
    #pragma unroll
    for (int i = 0; i < 4; i++) {
        m_i[i] = -1e30f; l_i[i] = 0.0f;
        #pragma unroll
        for (int d = 0; d < 4; d++) Oa[i][d] = 0.0f;
    }

    for (int kt = 0; kt < NK_ / 32; kt++) {
        __syncthreads();
        // load K (transposed) and V (row-major) tiles: 32 rows x 64 cols
        #pragma unroll
        for (int it = 0; it < 2; it++) {
            const int idx = tid + 256 * it;
            const int r = idx >> 4;            // 0..31
            const int c4 = (idx & 15) * 4;     // 0..60
            const size_t gr = (rowbase + kt * 32 + r) * DD + colbase + c4;
            float4 kk = *(const float4*)&k[gr];
            Ks[(c4 + 0) * 33 + r] = kk.x;
            Ks[(c4 + 1) * 33 + r] = kk.y;
            Ks[(c4 + 2) * 33 + r] = kk.z;
            Ks[(c4 + 3) * 33 + r] = kk.w;
            float4 vv = *(const float4*)&v[gr];
            *(float4*)&Vs[r * 68 + c4] = vv;
        }
        __syncthreads();

        // S = (Q K^T) * SCALE   (each thread 4x2)
        float s[4][2];
        #pragma unroll
        for (int i = 0; i < 4; i++) { s[i][0] = 0.f; s[i][1] = 0.f; }
        #pragma unroll 16
        for (int d = 0; d < 64; d++) {
            float qa[4], kb[2];
            #pragma unroll
            for (int i = 0; i < 4; i++) qa[i] = Qs[d * 65 + ty * 4 + i];
            kb[0] = Ks[d * 33 + tx * 2 + 0];
            kb[1] = Ks[d * 33 + tx * 2 + 1];
            #pragma unroll
            for (int i = 0; i < 4; i++) {
                s[i][0] = fmaf(qa[i], kb[0], s[i][0]);
                s[i][1] = fmaf(qa[i], kb[1], s[i][1]);
            }
        }

        // online softmax update
        #pragma unroll
        for (int i = 0; i < 4; i++) {
            s[i][0] *= SCALE_;
            s[i][1] *= SCALE_;
            float mx = fmaxf(s[i][0], s[i][1]);
            #pragma unroll
            for (int off = 8; off >= 1; off >>= 1)
                mx = fmaxf(mx, __shfl_xor_sync(0xffffffffu, mx, off));
            const float mn = fmaxf(m_i[i], mx);
            const float alpha = __expf(m_i[i] - mn);
            m_i[i] = mn;
            const float p0 = __expf(s[i][0] - mn);
            const float p1 = __expf(s[i][1] - mn);
            float rs = p0 + p1;
            #pragma unroll
            for (int off = 8; off >= 1; off >>= 1)
                rs += __shfl_xor_sync(0xffffffffu, rs, off);
            l_i[i] = l_i[i] * alpha + rs;
            #pragma unroll
            for (int d = 0; d < 4; d++) Oa[i][d] *= alpha;
            Ps[(ty * 4 + i) * 36 + tx * 2 + 0] = p0;
            Ps[(ty * 4 + i) * 36 + tx * 2 + 1] = p1;
        }
        __syncwarp();

        // O += P @ V   (each thread rows ty*4..+3, cols tx*4..+3)
        #pragma unroll 8
        for (int j = 0; j < 32; j++) {
            float pf[4];
            #pragma unroll
            for (int i = 0; i < 4; i++) pf[i] = Ps[(ty * 4 + i) * 36 + j];
            float4 vf = *(const float4*)&Vs[j * 68 + tx * 4];
            #pragma unroll
            for (int i = 0; i < 4; i++) {
                Oa[i][0] = fmaf(pf[i], vf.x, Oa[i][0]);
                Oa[i][1] = fmaf(pf[i], vf.y, Oa[i][1]);
                Oa[i][2] = fmaf(pf[i], vf.z, Oa[i][2]);
                Oa[i][3] = fmaf(pf[i], vf.w, Oa[i][3]);
            }
        }
        __syncwarp();
    }

    // finalize + store
    #pragma unroll
    for (int i = 0; i < 4; i++) {
        const float inv = 1.0f / l_i[i];
        float4 r;
        r.x = Oa[i][0] * inv; r.y = Oa[i][1] * inv;
        r.z = Oa[i][2] * inv; r.w = Oa[i][3] * inv;
        *(float4*)&o[(rowbase + q0 + ty * 4 + i) * DD + colbase + tx * 4] = r;
    }
}

// ---------------- fused residual add + LayerNorm ----------------------------
// one block per row (D=1024), 256 threads, float4 per thread.
__global__ void __launch_bounds__(256) add_ln_kernel(
    const float* __restrict__ a, const float* __restrict__ b,
    const float* __restrict__ g, const float* __restrict__ be,
    float* __restrict__ out)
{
    __shared__ float red_s[8];
    __shared__ float red_q[8];
    const int row = blockIdx.x;
    const int tid = threadIdx.x;
    const float4* a4 = (const float4*)(a + (size_t)row * DD);
    const float4* b4 = (const float4*)(b + (size_t)row * DD);

    float4 xa = a4[tid];
    float4 xb = b4[tid];
    float4 x;
    x.x = xa.x + xb.x; x.y = xa.y + xb.y;
    x.z = xa.z + xb.z; x.w = xa.w + xb.w;

    float s  = x.x + x.y + x.z + x.w;
    float ss = x.x * x.x + x.y * x.y + x.z * x.z + x.w * x.w;
    #pragma unroll
    for (int off = 16; off >= 1; off >>= 1) {
        s  += __shfl_xor_sync(0xffffffffu, s, off);
        ss += __shfl_xor_sync(0xffffffffu, ss, off);
    }
    const int wid = tid >> 5;
    if ((tid & 31) == 0) { red_s[wid] = s; red_q[wid] = ss; }
    __syncthreads();
    float tot = 0.f, tot2 = 0.f;
    #pragma unroll
    for (int w = 0; w < 8; w++) { tot += red_s[w]; tot2 += red_q[w]; }

    const float mu = tot * (1.0f / DD);
    const float var = tot2 * (1.0f / DD) - mu * mu;
    const float rstd = rsqrtf(var + LN_EPS);

    float4 gg = ((const float4*)g)[tid];
    float4 bb = ((const float4*)be)[tid];
    float4 r;
    r.x = (x.x - mu) * rstd * gg.x + bb.x;
    r.y = (x.y - mu) * rstd * gg.y + bb.y;
    r.z = (x.z - mu) * rstd * gg.z + bb.z;
    r.w = (x.w - mu) * rstd * gg.w + bb.w;
    ((float4*)(out + (size_t)row * DD))[tid] = r;
}

// ---------------- launcher ---------------------------------------------------
extern "C" void kernel_launch(void* const* d_in, const int* in_sizes, int n_in,
                              void* d_out, int out_size)
{
    const float* Q   = (const float*)d_in[0];
    const float* K   = (const float*)d_in[1];
    const float* Wq  = (const float*)d_in[2];
    const float* bq  = (const float*)d_in[3];
    const float* Wk  = (const float*)d_in[4];
    const float* bk  = (const float*)d_in[5];
    const float* Wv  = (const float*)d_in[6];
    const float* bv  = (const float*)d_in[7];
    const float* Wo  = (const float*)d_in[8];
    const float* bo  = (const float*)d_in[9];
    const float* W1  = (const float*)d_in[10];
    const float* b1  = (const float*)d_in[11];
    const float* W2  = (const float*)d_in[12];
    const float* b2  = (const float*)d_in[13];
    const float* g0  = (const float*)d_in[14];
    const float* be0 = (const float*)d_in[15];
    const float* g1  = (const float*)d_in[16];
    const float* be1 = (const float*)d_in[17];
    float* out = (float*)d_out;

    float *q, *k, *v, *o, *t, *x, *hb;
    cudaGetSymbolAddress((void**)&q,  g_q);
    cudaGetSymbolAddress((void**)&k,  g_k);
    cudaGetSymbolAddress((void**)&v,  g_v);
    cudaGetSymbolAddress((void**)&o,  g_o);
    cudaGetSymbolAddress((void**)&t,  g_t);
    cudaGetSymbolAddress((void**)&x,  g_x);
    cudaGetSymbolAddress((void**)&hb, g_h);

    const dim3 gN1024(DD / 128, M_ROWS / 128);     // N=1024 GEMMs
    const dim3 gN4096(DFF_ / 128, M_ROWS / 128);   // N=4096 GEMM

    // QKV projections
    sgemm_kernel<0><<<gN1024, 256>>>(Q, Wq, bq, q, M_ROWS, DD, DD);
    sgemm_kernel<0><<<gN1024, 256>>>(K, Wk, bk, k, M_ROWS, DD, DD);
    sgemm_kernel<0><<<gN1024, 256>>>(K, Wv, bv, v, M_ROWS, DD, DD);

    // attention
    attn_kernel<<<dim3(NQ_ / 64, HH, BB), 256>>>(q, k, v, o);

    // output projection, residual + LN0
    sgemm_kernel<0><<<gN1024, 256>>>(o, Wo, bo, t, M_ROWS, DD, DD);
    add_ln_kernel<<<M_ROWS, 256>>>(Q, t, g0, be0, x);

    // FFN
    sgemm_kernel<1><<<gN4096, 256>>>(x, W1, b1, hb, M_ROWS, DFF_, DD);
    sgemm_kernel<0><<<gN1024, 256>>>(hb, W2, b2, t, M_ROWS, DD, DFF_);

    // residual + LN1 -> output
    add_ln_kernel<<<M_ROWS, 256>>>(x, t, g1, be1, out);
}

// round 3
// speedup vs baseline: 2.3791x; 2.3791x over previous
#include <cuda_runtime.h>
#include <cuda_bf16.h>
#include <cstdint>

// ---------------- problem constants ----------------
#define BB   4
#define NQ_  1024
#define DD   1024
#define HH   16
#define DH_  64
#define DFF_ 4096
#define MR   4096            // B*NQ rows
#define SCALE_ (1.0f / 32.0f)
#define LN_EPS 1e-5f

// ================= PTX helpers =================
__device__ __forceinline__ uint32_t smem_u32(const void* p) {
    uint32_t a;
    asm("{ .reg .u64 t; cvta.to.shared.u64 t, %1; cvt.u32.u64 %0, t; }" : "=r"(a) : "l"(p));
    return a;
}
#define MBAR_INIT(addr, cnt) \
    asm volatile("mbarrier.init.shared.b64 [%0], %1;" :: "r"(addr), "r"(cnt) : "memory")
#define MBAR_EXPECT_TX(addr, bytes) \
    asm volatile("mbarrier.arrive.expect_tx.shared.b64 _, [%0], %1;" :: "r"(addr), "r"(bytes) : "memory")
#define MBAR_ARRIVE(addr) \
    asm volatile("mbarrier.arrive.shared.b64 _, [%0];" :: "r"(addr) : "memory")
#define MBAR_WAIT(addr, parity) do {                                          \
    uint32_t _m = (addr); uint32_t _p = (parity); uint32_t _d;                \
    asm volatile("{\n\t.reg .pred p;\n\t"                                     \
        "mbarrier.try_wait.parity.shared.b64 p, [%1], %2;\n\t"                \
        "selp.b32 %0, 1, 0, p;\n\t}" : "=r"(_d) : "r"(_m), "r"(_p) : "memory"); \
    if (!_d) {                                                                \
        asm volatile("{\n\t.reg .pred P1;\n\t"                                \
            "WL_%=:\n\t"                                                      \
            "mbarrier.try_wait.parity.shared.b64 P1, [%0], %1;\n\t"           \
            "@P1 bra.uni WD_%=;\n\t"                                          \
            "bra.uni WL_%=;\n\t"                                              \
            "WD_%=:\n\t}" :: "r"(_m), "r"(_p) : "memory");                    \
    } } while (0)

__device__ __forceinline__ void bulk_g2s(uint32_t dst, const void* src, uint32_t bytes, uint32_t mbar) {
    asm volatile("cp.async.bulk.shared::cluster.global.mbarrier::complete_tx::bytes [%0], [%1], %2, [%3];"
        :: "r"(dst), "l"(src), "r"(bytes), "r"(mbar) : "memory");
}
__device__ __forceinline__ uint32_t sw128(uint32_t off) { return off ^ ((off >> 3) & 0x70); }
__device__ __forceinline__ uint32_t pack2(__nv_bfloat16 a, __nv_bfloat16 b) {
    return (uint32_t)__bfloat16_as_ushort(a) | ((uint32_t)__bfloat16_as_ushort(b) << 16);
}

#define LDSM_X4(r0, r1, r2, r3, addr) \
    asm volatile("ldmatrix.sync.aligned.m8n8.x4.shared.b16 {%0,%1,%2,%3}, [%4];" \
        : "=r"(r0), "=r"(r1), "=r"(r2), "=r"(r3) : "r"(addr))

__device__ __forceinline__ void mma_bf16(float* c, uint32_t a0, uint32_t a1, uint32_t a2, uint32_t a3,
                                         uint32_t b0, uint32_t b1) {
    asm volatile("mma.sync.aligned.m16n8k16.row.col.f32.bf16.bf16.f32 "
        "{%0,%1,%2,%3}, {%4,%5,%6,%7}, {%8,%9}, {%0,%1,%2,%3};"
        : "+f"(c[0]), "+f"(c[1]), "+f"(c[2]), "+f"(c[3])
        : "r"(a0), "r"(a1), "r"(a2), "r"(a3), "r"(b0), "r"(b1));
}

// ================= scratch pools (static; no allocs) =================
#define SZA (4096ull * 1024ull)
#define SZH (4096ull * 4096ull)
__device__ float g_f32[6 * SZA + SZH];
#define OF_Q 0
#define OF_K (1 * SZA)
#define OF_V (2 * SZA)
#define OF_O (3 * SZA)
#define OF_T (4 * SZA)
#define OF_X (5 * SZA)
#define OF_H (6 * SZA)
#define SZW (1024ull * 1024ull)
#define O_PQ_HI (0 * SZA)
#define O_PQ_LO (1 * SZA)
#define O_PK_HI (2 * SZA)
#define O_PK_LO (3 * SZA)
#define O_PO_HI (4 * SZA)
#define O_PO_LO (5 * SZA)
#define O_PX_HI (6 * SZA)
#define O_PX_LO (7 * SZA)
#define O_PH_HI (8 * SZA)
#define O_PH_LO (8 * SZA + SZH)
#define O_WBASE (8 * SZA + 2 * SZH)
#define O_WQ_HI (O_WBASE + 0 * SZW)
#define O_WQ_LO (O_WBASE + 1 * SZW)
#define O_WK_HI (O_WBASE + 2 * SZW)
#define O_WK_LO (O_WBASE + 3 * SZW)
#define O_WV_HI (O_WBASE + 4 * SZW)
#define O_WV_LO (O_WBASE + 5 * SZW)
#define O_WO_HI (O_WBASE + 6 * SZW)
#define O_WO_LO (O_WBASE + 7 * SZW)
#define O_W1_HI (O_WBASE + 8 * SZW)
#define O_W1_LO (O_W1_HI + SZA)
#define O_W2_HI (O_W1_LO + SZA)
#define O_W2_LO (O_W2_HI + SZA)
__device__ __nv_bfloat16 g_bf[O_W2_LO + SZA];

// ================= pack activations: fp32 [M,K] -> hi/lo blocks =============
// block (mt,kt) = 128 rows x 64 k, SW128-swizzled 16KB image, linear idx mt*nkt+kt
__global__ void __launch_bounds__(256) pack_a_kernel(
    const float* __restrict__ X, __nv_bfloat16* __restrict__ hi,
    __nv_bfloat16* __restrict__ lo, int nkt, int K)
{
    const int kt = blockIdx.x, mt = blockIdx.y;
    const size_t blk_bytes = ((size_t)mt * nkt + kt) * 16384ull;
    const int tid = threadIdx.x;
    #pragma unroll
    for (int it = 0; it < 4; it++) {
        const int u = tid + 256 * it;        // 0..1023
        const int m = u >> 3, k8 = u & 7;
        const float* src = X + ((size_t)(mt * 128 + m)) * K + kt * 64 + k8 * 8;
        float4 a = *(const float4*)src;
        float4 b = *(const float4*)(src + 4);
        float f[8] = {a.x, a.y, a.z, a.w, b.x, b.y, b.z, b.w};
        uint32_t hh[4], ll[4];
        #pragma unroll
        for (int i = 0; i < 4; i++) {
            __nv_bfloat16 h0 = __float2bfloat16(f[2 * i]);
            __nv_bfloat16 h1 = __float2bfloat16(f[2 * i + 1]);
            __nv_bfloat16 l0 = __float2bfloat16(f[2 * i] - __bfloat162float(h0));
            __nv_bfloat16 l1 = __float2bfloat16(f[2 * i + 1] - __bfloat162float(h1));
            hh[i] = pack2(h0, h1);
            ll[i] = pack2(l0, l1);
        }
        const uint32_t boff = sw128((uint32_t)(m * 128 + k8 * 16));
        *(uint4*)((char*)hi + blk_bytes + boff) = make_uint4(hh[0], hh[1], hh[2], hh[3]);
        *(uint4*)((char*)lo + blk_bytes + boff) = make_uint4(ll[0], ll[1], ll[2], ll[3]);
    }
}

// ================= pack weights: fp32 W[K,N] -> transposed hi/lo blocks =====
__global__ void __launch_bounds__(256) pack_w_kernel(
    const float* __restrict__ W, __nv_bfloat16* __restrict__ hi,
    __nv_bfloat16* __restrict__ lo, int nkt, int N)
{
    __shared__ float sm[64][132];
    const int kt = blockIdx.x, nt = blockIdx.y;
    const int tid = threadIdx.x;
    #pragma unroll
    for (int it = 0; it < 8; it++) {
        const int f = tid + 256 * it;        // 0..2047 float4 units
        const int row = f >> 5, c4 = f & 31;
        float4 v = *(const float4*)&W[((size_t)(kt * 64 + row)) * N + nt * 128 + c4 * 4];
        *(float4*)&sm[row][c4 * 4] = v;
    }
    __syncthreads();
    const size_t blk_bytes = ((size_t)nt * nkt + kt) * 16384ull;
    #pragma unroll
    for (int it = 0; it < 4; it++) {
        const int u = tid + 256 * it;        // 0..1023
        const int k8 = u >> 7, n = u & 127;
        uint32_t hh[4], ll[4];
        #pragma unroll
        for (int i = 0; i < 4; i++) {
            float f0 = sm[k8 * 8 + 2 * i][n];
            float f1 = sm[k8 * 8 + 2 * i + 1][n];
            __nv_bfloat16 h0 = __float2bfloat16(f0);
            __nv_bfloat16 h1 = __float2bfloat16(f1);
            __nv_bfloat16 l0 = __float2bfloat16(f0 - __bfloat162float(h0));
            __nv_bfloat16 l1 = __float2bfloat16(f1 - __bfloat162float(h1));
            hh[i] = pack2(h0, h1);
            ll[i] = pack2(l0, l1);
        }
        const uint32_t boff = sw128((uint32_t)(n * 128 + k8 * 16));
        *(uint4*)((char*)hi + blk_bytes + boff) = make_uint4(hh[0], hh[1], hh[2], hh[3]);
        *(uint4*)((char*)lo + blk_bytes + boff) = make_uint4(ll[0], ll[1], ll[2], ll[3]);
    }
}

// ================= mma.sync bf16x3 GEMM =====================================
// C[M,N] = (Ahi+Alo)[M,K] @ (Bhi+Blo)^T[N,K] + bias
// BM=BN=128, BK=64, 3 stages x 64KB, 256 threads (8 warps of 64x32).
#define STG_BYTES 65536
#define BAR_OFF   (3 * STG_BYTES)          // 196608
#define SMEM_GEMM (BAR_OFF + 64)

template <int RELU>
__global__ void __launch_bounds__(256, 1) tcmm_kernel(
    const __nv_bfloat16* __restrict__ Ahi, const __nv_bfloat16* __restrict__ Alo,
    const __nv_bfloat16* __restrict__ Bhi, const __nv_bfloat16* __restrict__ Blo,
    const float* __restrict__ bias, float* __restrict__ C,
    int nkt, int N)
{
    extern __shared__ __align__(1024) char smem[];
    const uint32_t sb = smem_u32(smem);
    const int tid = threadIdx.x;
    const int wid = tid >> 5, lane = tid & 31;
    const int wm = wid >> 2, wn = wid & 3;           // 2 x 4 warp grid
    const int mt = blockIdx.y, nt = blockIdx.x;

    if (tid == 0) {
        #pragma unroll
        for (int s = 0; s < 3; s++) {
            MBAR_INIT(sb + BAR_OFF + s * 8, 1);        // full (producer expect_tx)
            MBAR_INIT(sb + BAR_OFF + 24 + s * 8, 256); // empty (all threads arrive)
        }
        asm volatile("fence.proxy.async.shared::cta;" ::: "memory");
    }
    __syncthreads();

    const size_t ablk = (size_t)mt * nkt;
    const size_t bblk = (size_t)nt * nkt;
    if (tid == 0) {
        #pragma unroll
        for (int c = 0; c < 3; c++) {
            const uint32_t st = sb + c * STG_BYTES;
            const uint32_t fb = sb + BAR_OFF + c * 8;
            MBAR_EXPECT_TX(fb, STG_BYTES);
            bulk_g2s(st,         (const char*)Ahi + (ablk + c) * 16384ull, 16384, fb);
            bulk_g2s(st + 16384, (const char*)Alo + (ablk + c) * 16384ull, 16384, fb);
            bulk_g2s(st + 32768, (const char*)Bhi + (bblk + c) * 16384ull, 16384, fb);
            bulk_g2s(st + 49152, (const char*)Blo + (bblk + c) * 16384ull, 16384, fb);
        }
    }

    // per-lane ldmatrix row offsets (within 128-row, 128B-pitch swizzled image)
    const int a_row = wm * 64 + (lane & 15);          // + mt16*16
    const int a_kg  = (lane >> 4) * 16;               // 16B col within k16 pair
    const int b_row = wn * 32 + ((lane >> 4) * 8) + (lane & 7);  // + nt2*16
    const int b_kg  = ((lane >> 3) & 1) * 16;

    float acc[4][4][4];
    #pragma unroll
    for (int i = 0; i < 4; i++)
        #pragma unroll
        for (int j = 0; j < 4; j++)
            #pragma unroll
            for (int q = 0; q < 4; q++) acc[i][j][q] = 0.0f;

    for (int c = 0; c < nkt; c++) {
        const int s = c - (c / 3) * 3;
        const uint32_t ph = (uint32_t)((c / 3) & 1);
        MBAR_WAIT(sb + BAR_OFF + s * 8, ph);
        const uint32_t aH = sb + s * STG_BYTES;
        const uint32_t aL = aH + 16384;
        const uint32_t bH = aH + 32768;
        const uint32_t bL = aH + 49152;

        #pragma unroll
        for (int k16 = 0; k16 < 4; k16++) {
            const int kb = k16 * 32;
            uint32_t ahi[4][4], alo[4][4], bhi[2][4], blo[2][4];
            #pragma unroll
            for (int m4 = 0; m4 < 4; m4++) {
                const uint32_t off = sw128((uint32_t)((a_row + m4 * 16) * 128 + a_kg + kb));
                LDSM_X4(ahi[m4][0], ahi[m4][1], ahi[m4][2], ahi[m4][3], aH + off);
                LDSM_X4(alo[m4][0], alo[m4][1], alo[m4][2], alo[m4][3], aL + off);
            }
            #pragma unroll
            for (int n2 = 0; n2 < 2; n2++) {
                const uint32_t off = sw128((uint32_t)((b_row + n2 * 16) * 128 + b_kg + kb));
                LDSM_X4(bhi[n2][0], bhi[n2][1], bhi[n2][2], bhi[n2][3], bH + off);
                LDSM_X4(blo[n2][0], blo[n2][1], blo[n2][2], blo[n2][3], bL + off);
            }
            #pragma unroll
            for (int m4 = 0; m4 < 4; m4++)
                #pragma unroll
                for (int n8 = 0; n8 < 4; n8++) {
                    const int n2 = n8 >> 1, sel = (n8 & 1) * 2;
                    mma_bf16(acc[m4][n8], ahi[m4][0], ahi[m4][1], ahi[m4][2], ahi[m4][3],
                             bhi[n2][sel], bhi[n2][sel + 1]);
                    mma_bf16(acc[m4][n8], ahi[m4][0], ahi[m4][1], ahi[m4][2], ahi[m4][3],
                             blo[n2][sel], blo[n2][sel + 1]);
                    mma_bf16(acc[m4][n8], alo[m4][0], alo[m4][1], alo[m4][2], alo[m4][3],
                             bhi[n2][sel], bhi[n2][sel + 1]);
                }
        }
        MBAR_ARRIVE(sb + BAR_OFF + 24 + s * 8);
        if (tid == 0 && c + 3 < nkt) {
            MBAR_WAIT(sb + BAR_OFF + 24 + s * 8, ph);   // all 256 arrived
            const uint32_t st = sb + s * STG_BYTES;
            const uint32_t fb = sb + BAR_OFF + s * 8;
            MBAR_EXPECT_TX(fb, STG_BYTES);
            bulk_g2s(st,         (const char*)Ahi + (ablk + c + 3) * 16384ull, 16384, fb);
            bulk_g2s(st + 16384, (const char*)Alo + (ablk + c + 3) * 16384ull, 16384, fb);
            bulk_g2s(st + 32768, (const char*)Bhi + (bblk + c + 3) * 16384ull, 16384, fb);
            bulk_g2s(st + 49152, (const char*)Blo + (bblk + c + 3) * 16384ull, 16384, fb);
        }
    }

    // epilogue: fragment -> global, + bias (+ReLU)
    const int g = lane >> 2, tig = lane & 3;
    const int row_base = mt * 128 + wm * 64;
    const int col_base = nt * 128 + wn * 32;
    #pragma unroll
    for (int n8 = 0; n8 < 4; n8++) {
        const int col = col_base + n8 * 8 + tig * 2;
        float2 bv = *(const float2*)&bias[col];
        #pragma unroll
        for (int m4 = 0; m4 < 4; m4++) {
            const size_t r0 = (size_t)(row_base + m4 * 16 + g);
            float2 v0, v1;
            v0.x = acc[m4][n8][0] + bv.x;
            v0.y = acc[m4][n8][1] + bv.y;
            v1.x = acc[m4][n8][2] + bv.x;
            v1.y = acc[m4][n8][3] + bv.y;
            if (RELU) {
                v0.x = fmaxf(v0.x, 0.f); v0.y = fmaxf(v0.y, 0.f);
                v1.x = fmaxf(v1.x, 0.f); v1.y = fmaxf(v1.y, 0.f);
            }
            *(float2*)&C[r0 * N + col] = v0;
            *(float2*)&C[(r0 + 8) * N + col] = v1;
        }
    }
}

// ================= flash attention (fp32) ===================================
__global__ void __launch_bounds__(256) attn_kernel(
    const float* __restrict__ q, const float* __restrict__ k,
    const float* __restrict__ v, float* __restrict__ o)
{
    __shared__ float Qs[64 * 65];
    __shared__ float Ks[64 * 33];
    __shared__ float Vs[32 * 68];
    __shared__ float Ps[64 * 36];

    const int tid = threadIdx.x;
    const int ty = tid >> 4;
    const int tx = tid & 15;
    const int q0 = blockIdx.x * 64;
    const int h  = blockIdx.y;
    const int b  = blockIdx.z;

    const size_t rowbase = (size_t)b * NQ_;
    const int colbase = h * DH_;

    #pragma unroll
    for (int it = 0; it < 4; it++) {
        const int r = ty + 16 * it;
        float4 t = *(const float4*)&q[(rowbase + q0 + r) * DD + colbase + tx * 4];
        Qs[(tx * 4 + 0) * 65 + r] = t.x;
        Qs[(tx * 4 + 1) * 65 + r] = t.y;
        Qs[(tx * 4 + 2) * 65 + r] = t.z;
        Qs[(tx * 4 + 3) * 65 + r] = t.w;
    }

    float m_i[4], l_i[4], Oa[4][4];
    #pragma unroll
    for (int i = 0; i < 4; i++) {
        m_i[i] = -1e30f; l_i[i] = 0.0f;
        #pragma unroll
        for (int d = 0; d < 4; d++) Oa[i][d] = 0.0f;
    }

    for (int kt = 0; kt < NQ_ / 32; kt++) {
        __syncthreads();
        #pragma unroll
        for (int it = 0; it < 2; it++) {
            const int idx = tid + 256 * it;
            const int r = idx >> 4;
            const int c4 = (idx & 15) * 4;
            const size_t gr = (rowbase + kt * 32 + r) * DD + colbase + c4;
            float4 kk = *(const float4*)&k[gr];
            Ks[(c4 + 0) * 33 + r] = kk.x;
            Ks[(c4 + 1) * 33 + r] = kk.y;
            Ks[(c4 + 2) * 33 + r] = kk.z;
            Ks[(c4 + 3) * 33 + r] = kk.w;
            float4 vv = *(const float4*)&v[gr];
            *(float4*)&Vs[r * 68 + c4] = vv;
        }
        __syncthreads();

        float s[4][2];
        #pragma unroll
        for (int i = 0; i < 4; i++) { s[i][0] = 0.f; s[i][1] = 0.f; }
        #pragma unroll 16
        for (int d = 0; d < 64; d++) {
            float qa[4], kb[2];
            #pragma unroll
            for (int i = 0; i < 4; i++) qa[i] = Qs[d * 65 + ty * 4 + i];
            kb[0] = Ks[d * 33 + tx * 2 + 0];
            kb[1] = Ks[d * 33 + tx * 2 + 1];
            #pragma unroll
            for (int i = 0; i < 4; i++) {
                s[i][0] = fmaf(qa[i], kb[0], s[i][0]);
                s[i][1] = fmaf(qa[i], kb[1], s[i][1]);
            }
        }

        #pragma unroll
        for (int i = 0; i < 4; i++) {
            s[i][0] *= SCALE_;
            s[i][1] *= SCALE_;
            float mx = fmaxf(s[i][0], s[i][1]);
            #pragma unroll
            for (int off = 8; off >= 1; off >>= 1)
                mx = fmaxf(mx, __shfl_xor_sync(0xffffffffu, mx, off));
            const float mn = fmaxf(m_i[i], mx);
            const float alpha = __expf(m_i[i] - mn);
            m_i[i] = mn;
            const float p0 = __expf(s[i][0] - mn);
            const float p1 = __expf(s[i][1] - mn);
            float rs = p0 + p1;
            #pragma unroll
            for (int off = 8; off >= 1; off >>= 1)
                rs += __shfl_xor_sync(0xffffffffu, rs, off);
            l_i[i] = l_i[i] * alpha + rs;
            #pragma unroll
            for (int d = 0; d < 4; d++) Oa[i][d] *= alpha;
            Ps[(ty * 4 + i) * 36 + tx * 2 + 0] = p0;
            Ps[(ty * 4 + i) * 36 + tx * 2 + 1] = p1;
        }
        __syncwarp();

        #pragma unroll 8
        for (int j = 0; j < 32; j++) {
            float pf[4];
            #pragma unroll
            for (int i = 0; i < 4; i++) pf[i] = Ps[(ty * 4 + i) * 36 + j];
            float4 vf = *(const float4*)&Vs[j * 68 + tx * 4];
            #pragma unroll
            for (int i = 0; i < 4; i++) {
                Oa[i][0] = fmaf(pf[i], vf.x, Oa[i][0]);
                Oa[i][1] = fmaf(pf[i], vf.y, Oa[i][1]);
                Oa[i][2] = fmaf(pf[i], vf.z, Oa[i][2]);
                Oa[i][3] = fmaf(pf[i], vf.w, Oa[i][3]);
            }
        }
        __syncwarp();
    }

    #pragma unroll
    for (int i = 0; i < 4; i++) {
        const float inv = 1.0f / l_i[i];
        float4 r;
        r.x = Oa[i][0] * inv; r.y = Oa[i][1] * inv;
        r.z = Oa[i][2] * inv; r.w = Oa[i][3] * inv;
        *(float4*)&o[(rowbase + q0 + ty * 4 + i) * DD + colbase + tx * 4] = r;
    }
}

// ================= fused residual add + LayerNorm ===========================
__global__ void __launch_bounds__(256) add_ln_kernel(
    const float* __restrict__ a, const float* __restrict__ b,
    const float* __restrict__ g, const float* __restrict__ be,
    float* __restrict__ out)
{
    __shared__ float red_s[8];
    __shared__ float red_q[8];
    const int row = blockIdx.x;
    const int tid = threadIdx.x;
    const float4* a4 = (const float4*)(a + (size_t)row * DD);
    const float4* b4 = (const float4*)(b + (size_t)row * DD);

    float4 xa = a4[tid];
    float4 xb = b4[tid];
    float4 x;
    x.x = xa.x + xb.x; x.y = xa.y + xb.y;
    x.z = xa.z + xb.z; x.w = xa.w + xb.w;

    float s  = x.x + x.y + x.z + x.w;
    float ss = x.x * x.x + x.y * x.y + x.z * x.z + x.w * x.w;
    #pragma unroll
    for (int off = 16; off >= 1; off >>= 1) {
        s  += __shfl_xor_sync(0xffffffffu, s, off);
        ss += __shfl_xor_sync(0xffffffffu, ss, off);
    }
    const int wid = tid >> 5;
    if ((tid & 31) == 0) { red_s[wid] = s; red_q[wid] = ss; }
    __syncthreads();
    float tot = 0.f, tot2 = 0.f;
    #pragma unroll
    for (int w = 0; w < 8; w++) { tot += red_s[w]; tot2 += red_q[w]; }

    const float mu = tot * (1.0f / DD);
    const float var = tot2 * (1.0f / DD) - mu * mu;
    const float rstd = rsqrtf(var + LN_EPS);

    float4 gg = ((const float4*)g)[tid];
    float4 bb = ((const float4*)be)[tid];
    float4 r;
    r.x = (x.x - mu) * rstd * gg.x + bb.x;
    r.y = (x.y - mu) * rstd * gg.y + bb.y;
    r.z = (x.z - mu) * rstd * gg.z + bb.z;
    r.w = (x.w - mu) * rstd * gg.w + bb.w;
    ((float4*)(out + (size_t)row * DD))[tid] = r;
}

// ================= launcher ==================================================
extern "C" void kernel_launch(void* const* d_in, const int* in_sizes, int n_in,
                              void* d_out, int out_size)
{
    const float* Q   = (const float*)d_in[0];
    const float* K   = (const float*)d_in[1];
    const float* Wq  = (const float*)d_in[2];
    const float* bq  = (const float*)d_in[3];
    const float* Wk  = (const float*)d_in[4];
    const float* bk  = (const float*)d_in[5];
    const float* Wv  = (const float*)d_in[6];
    const float* bv  = (const float*)d_in[7];
    const float* Wo  = (const float*)d_in[8];
    const float* bo  = (const float*)d_in[9];
    const float* W1  = (const float*)d_in[10];
    const float* b1  = (const float*)d_in[11];
    const float* W2  = (const float*)d_in[12];
    const float* b2  = (const float*)d_in[13];
    const float* g0  = (const float*)d_in[14];
    const float* be0 = (const float*)d_in[15];
    const float* g1  = (const float*)d_in[16];
    const float* be1 = (const float*)d_in[17];
    float* out = (float*)d_out;

    float* F; __nv_bfloat16* P;
    cudaGetSymbolAddress((void**)&F, g_f32);
    cudaGetSymbolAddress((void**)&P, g_bf);

    static int smem_set = 0;
    if (!smem_set) {
        cudaFuncSetAttribute(tcmm_kernel<0>,
                             cudaFuncAttributeMaxDynamicSharedMemorySize, SMEM_GEMM);
        cudaFuncSetAttribute(tcmm_kernel<1>,
                             cudaFuncAttributeMaxDynamicSharedMemorySize, SMEM_GEMM);
        smem_set = 1;
    }

    // ---- pack weights (transpose to K-major, hi/lo split) ----
    pack_w_kernel<<<dim3(16, 8),  256>>>(Wq, P + O_WQ_HI, P + O_WQ_LO, 16, DD);
    pack_w_kernel<<<dim3(16, 8),  256>>>(Wk, P + O_WK_HI, P + O_WK_LO, 16, DD);
    pack_w_kernel<<<dim3(16, 8),  256>>>(Wv, P + O_WV_HI, P + O_WV_LO, 16, DD);
    pack_w_kernel<<<dim3(16, 8),  256>>>(Wo, P + O_WO_HI, P + O_WO_LO, 16, DD);
    pack_w_kernel<<<dim3(16, 32), 256>>>(W1, P + O_W1_HI, P + O_W1_LO, 16, DFF_);
    pack_w_kernel<<<dim3(64, 8),  256>>>(W2, P + O_W2_HI, P + O_W2_LO, 64, DD);

    // ---- pack input activations ----
    pack_a_kernel<<<dim3(16, 32), 256>>>(Q, P + O_PQ_HI, P + O_PQ_LO, 16, DD);
    pack_a_kernel<<<dim3(16, 32), 256>>>(K, P + O_PK_HI, P + O_PK_LO, 16, DD);

    // ---- QKV projections ----
    tcmm_kernel<0><<<dim3(8, 32), 256, SMEM_GEMM>>>(
        P + O_PQ_HI, P + O_PQ_LO, P + O_WQ_HI, P + O_WQ_LO, bq, F + OF_Q, 16, DD);
    tcmm_kernel<0><<<dim3(8, 32), 256, SMEM_GEMM>>>(
        P + O_PK_HI, P + O_PK_LO, P + O_WK_HI, P + O_WK_LO, bk, F + OF_K, 16, DD);
    tcmm_kernel<0><<<dim3(8, 32), 256, SMEM_GEMM>>>(
        P + O_PK_HI, P + O_PK_LO, P + O_WV_HI, P + O_WV_LO, bv, F + OF_V, 16, DD);

    // ---- attention ----
    attn_kernel<<<dim3(NQ_ / 64, HH, BB), 256>>>(F + OF_Q, F + OF_K, F + OF_V, F + OF_O);

    // ---- output projection + residual/LN0 ----
    pack_a_kernel<<<dim3(16, 32), 256>>>(F + OF_O, P + O_PO_HI, P + O_PO_LO, 16, DD);
    tcmm_kernel<0><<<dim3(8, 32), 256, SMEM_GEMM>>>(
        P + O_PO_HI, P + O_PO_LO, P + O_WO_HI, P + O_WO_LO, bo, F + OF_T, 16, DD);
    add_ln_kernel<<<MR, 256>>>(Q, F + OF_T, g0, be0, F + OF_X);

    // ---- FFN ----
    pack_a_kernel<<<dim3(16, 32), 256>>>(F + OF_X, P + O_PX_HI, P + O_PX_LO, 16, DD);
    tcmm_kernel<1><<<dim3(32, 32), 256, SMEM_GEMM>>>(
        P + O_PX_HI, P + O_PX_LO, P + O_W1_HI, P + O_W1_LO, b1, F + OF_H, 16, DFF_);
    pack_a_kernel<<<dim3(64, 32), 256>>>(F + OF_H, P + O_PH_HI, P + O_PH_LO, 64, DFF_);
    tcmm_kernel<0><<<dim3(8, 32), 256, SMEM_GEMM>>>(
        P + O_PH_HI, P + O_PH_LO, P + O_W2_HI, P + O_W2_LO, b2, F + OF_T, 64, DD);

    // ---- residual + LN1 -> output ----
    add_ln_kernel<<<MR, 256>>>(F + OF_X, F + OF_T, g1, be1, out);
}

// round 4
// speedup vs baseline: 3.3330x; 1.4009x over previous
#include <cuda_runtime.h>
#include <cuda_bf16.h>
#include <cstdint>

// ---------------- problem constants ----------------
#define BB   4
#define NQ_  1024
#define DD   1024
#define HH   16
#define DH_  64
#define DFF_ 4096
#define MR   4096
#define SCALE_ (1.0f / 32.0f)
#define LN_EPS 1e-5f

// ================= PTX helpers =================
__device__ __forceinline__ uint32_t smem_u32(const void* p) {
    uint32_t a;
    asm("{ .reg .u64 t; cvta.to.shared.u64 t, %1; cvt.u32.u64 %0, t; }" : "=r"(a) : "l"(p));
    return a;
}
#define MBAR_INIT(addr, cnt) \
    asm volatile("mbarrier.init.shared.b64 [%0], %1;" :: "r"(addr), "r"(cnt) : "memory")
#define MBAR_EXPECT_TX(addr, bytes) \
    asm volatile("mbarrier.arrive.expect_tx.shared.b64 _, [%0], %1;" :: "r"(addr), "r"(bytes) : "memory")
#define MBAR_ARRIVE(addr) \
    asm volatile("mbarrier.arrive.shared.b64 _, [%0];" :: "r"(addr) : "memory")
#define MBAR_WAIT(addr, parity) do {                                          \
    uint32_t _m = (addr); uint32_t _p = (parity); uint32_t _d;                \
    asm volatile("{\n\t.reg .pred p;\n\t"                                     \
        "mbarrier.try_wait.parity.shared.b64 p, [%1], %2;\n\t"                \
        "selp.b32 %0, 1, 0, p;\n\t}" : "=r"(_d) : "r"(_m), "r"(_p) : "memory"); \
    if (!_d) {                                                                \
        asm volatile("{\n\t.reg .pred P1;\n\t"                                \
            "WL_%=:\n\t"                                                      \
            "mbarrier.try_wait.parity.shared.b64 P1, [%0], %1;\n\t"           \
            "@P1 bra.uni WD_%=;\n\t"                                          \
            "bra.uni WL_%=;\n\t"                                              \
            "WD_%=:\n\t}" :: "r"(_m), "r"(_p) : "memory");                    \
    } } while (0)

__device__ __forceinline__ void bulk_g2s(uint32_t dst, const void* src, uint32_t bytes, uint32_t mbar) {
    asm volatile("cp.async.bulk.shared::cluster.global.mbarrier::complete_tx::bytes [%0], [%1], %2, [%3];"
        :: "r"(dst), "l"(src), "r"(bytes), "r"(mbar) : "memory");
}
__device__ __forceinline__ uint32_t sw128(uint32_t off) { return off ^ ((off >> 3) & 0x70); }
__device__ __forceinline__ uint32_t pack2(__nv_bfloat16 a, __nv_bfloat16 b) {
    return (uint32_t)__bfloat16_as_ushort(a) | ((uint32_t)__bfloat16_as_ushort(b) << 16);
}

#define LDSM_X4(r0, r1, r2, r3, addr) \
    asm volatile("ldmatrix.sync.aligned.m8n8.x4.shared.b16 {%0,%1,%2,%3}, [%4];" \
        : "=r"(r0), "=r"(r1), "=r"(r2), "=r"(r3) : "r"(addr))
#define LDSM_X4_T(r0, r1, r2, r3, addr) \
    asm volatile("ldmatrix.sync.aligned.m8n8.x4.trans.shared.b16 {%0,%1,%2,%3}, [%4];" \
        : "=r"(r0), "=r"(r1), "=r"(r2), "=r"(r3) : "r"(addr))

__device__ __forceinline__ void mma_bf16(float* c, uint32_t a0, uint32_t a1, uint32_t a2, uint32_t a3,
                                         uint32_t b0, uint32_t b1) {
    asm volatile("mma.sync.aligned.m16n8k16.row.col.f32.bf16.bf16.f32 "
        "{%0,%1,%2,%3}, {%4,%5,%6,%7}, {%8,%9}, {%0,%1,%2,%3};"
        : "+f"(c[0]), "+f"(c[1]), "+f"(c[2]), "+f"(c[3])
        : "r"(a0), "r"(a1), "r"(a2), "r"(a3), "r"(b0), "r"(b1));
}

// ================= scratch pools =================
#define E4M  (4096ull * 1024ull)
#define E16M (4096ull * 4096ull)
__device__ float g_f32[2 * E4M];
#define OF_T 0
#define OF_X E4M
// bf16 image pool (all 128x64 SW128 block images)
#define O_PQ_HI (0 * E4M)
#define O_PQ_LO (1 * E4M)
#define O_PK_HI (2 * E4M)
#define O_PK_LO (3 * E4M)
#define O_QP_HI (4 * E4M)
#define O_QP_LO (5 * E4M)
#define O_KP_HI (6 * E4M)
#define O_KP_LO (7 * E4M)
#define O_VP_HI (8 * E4M)
#define O_VP_LO (9 * E4M)
#define O_OP_HI (10 * E4M)
#define O_OP_LO (11 * E4M)
#define O_X_HI  (12 * E4M)
#define O_X_LO  (13 * E4M)
#define O_H_HI  (14 * E4M)
#define O_H_LO  (14 * E4M + E16M)
#define O_WBASE (14 * E4M + 2 * E16M)
#define SZW (1024ull * 1024ull)
#define O_WQ_HI (O_WBASE + 0 * SZW)
#define O_WQ_LO (O_WBASE + 1 * SZW)
#define O_WK_HI (O_WBASE + 2 * SZW)
#define O_WK_LO (O_WBASE + 3 * SZW)
#define O_WV_HI (O_WBASE + 4 * SZW)
#define O_WV_LO (O_WBASE + 5 * SZW)
#define O_WO_HI (O_WBASE + 6 * SZW)
#define O_WO_LO (O_WBASE + 7 * SZW)
#define O_W1_HI (O_WBASE + 8 * SZW)
#define O_W1_LO (O_W1_HI + E4M)
#define O_W2_HI (O_W1_LO + E4M)
#define O_W2_LO (O_W2_HI + E4M)
__device__ __nv_bfloat16 g_bf[O_W2_LO + E4M];

// ================= pack activations (inputs only) ===========================
__global__ void __launch_bounds__(256) pack_a_kernel(
    const float* __restrict__ X, __nv_bfloat16* __restrict__ hi,
    __nv_bfloat16* __restrict__ lo, int nkt, int K)
{
    const int kt = blockIdx.x, mt = blockIdx.y;
    const size_t blk_bytes = ((size_t)mt * nkt + kt) * 16384ull;
    const int tid = threadIdx.x;
    #pragma unroll
    for (int it = 0; it < 4; it++) {
        const int u = tid + 256 * it;
        const int m = u >> 3, k8 = u & 7;
        const float* src = X + ((size_t)(mt * 128 + m)) * K + kt * 64 + k8 * 8;
        float4 a = *(const float4*)src;
        float4 b = *(const float4*)(src + 4);
        float f[8] = {a.x, a.y, a.z, a.w, b.x, b.y, b.z, b.w};
        uint32_t hh[4], ll[4];
        #pragma unroll
        for (int i = 0; i < 4; i++) {
            __nv_bfloat16 h0 = __float2bfloat16(f[2 * i]);
            __nv_bfloat16 h1 = __float2bfloat16(f[2 * i + 1]);
            __nv_bfloat16 l0 = __float2bfloat16(f[2 * i] - __bfloat162float(h0));
            __nv_bfloat16 l1 = __float2bfloat16(f[2 * i + 1] - __bfloat162float(h1));
            hh[i] = pack2(h0, h1);
            ll[i] = pack2(l0, l1);
        }
        const uint32_t boff = sw128((uint32_t)(m * 128 + k8 * 16));
        *(uint4*)((char*)hi + blk_bytes + boff) = make_uint4(hh[0], hh[1], hh[2], hh[3]);
        *(uint4*)((char*)lo + blk_bytes + boff) = make_uint4(ll[0], ll[1], ll[2], ll[3]);
    }
}

// ================= pack weights =============================================
__global__ void __launch_bounds__(256) pack_w_kernel(
    const float* __restrict__ W, __nv_bfloat16* __restrict__ hi,
    __nv_bfloat16* __restrict__ lo, int nkt, int N)
{
    __shared__ float sm[64][132];
    const int kt = blockIdx.x, nt = blockIdx.y;
    const int tid = threadIdx.x;
    #pragma unroll
    for (int it = 0; it < 8; it++) {
        const int f = tid + 256 * it;
        const int row = f >> 5, c4 = f & 31;
        float4 v = *(const float4*)&W[((size_t)(kt * 64 + row)) * N + nt * 128 + c4 * 4];
        *(float4*)&sm[row][c4 * 4] = v;
    }
    __syncthreads();
    const size_t blk_bytes = ((size_t)nt * nkt + kt) * 16384ull;
    #pragma unroll
    for (int it = 0; it < 4; it++) {
        const int u = tid + 256 * it;
        const int k8 = u >> 7, n = u & 127;
        uint32_t hh[4], ll[4];
        #pragma unroll
        for (int i = 0; i < 4; i++) {
            float f0 = sm[k8 * 8 + 2 * i][n];
            float f1 = sm[k8 * 8 + 2 * i + 1][n];
            __nv_bfloat16 h0 = __float2bfloat16(f0);
            __nv_bfloat16 h1 = __float2bfloat16(f1);
            __nv_bfloat16 l0 = __float2bfloat16(f0 - __bfloat162float(h0));
            __nv_bfloat16 l1 = __float2bfloat16(f1 - __bfloat162float(h1));
            hh[i] = pack2(h0, h1);
            ll[i] = pack2(l0, l1);
        }
        const uint32_t boff = sw128((uint32_t)(n * 128 + k8 * 16));
        *(uint4*)((char*)hi + blk_bytes + boff) = make_uint4(hh[0], hh[1], hh[2], hh[3]);
        *(uint4*)((char*)lo + blk_bytes + boff) = make_uint4(ll[0], ll[1], ll[2], ll[3]);
    }
}

// ================= mma.sync bf16x3 GEMM =====================================
#define STG_BYTES 65536
#define BAR_OFF   (3 * STG_BYTES)
#define SMEM_GEMM (BAR_OFF + 64)

template <int RELU, int PACK>
__global__ void __launch_bounds__(256, 1) tcmm_kernel(
    const __nv_bfloat16* __restrict__ Ahi, const __nv_bfloat16* __restrict__ Alo,
    const __nv_bfloat16* __restrict__ Bhi, const __nv_bfloat16* __restrict__ Blo,
    const float* __restrict__ bias, float* __restrict__ C,
    __nv_bfloat16* __restrict__ Chi, __nv_bfloat16* __restrict__ Clo,
    int nkt, int N)
{
    extern __shared__ __align__(1024) char smem[];
    const uint32_t sb = smem_u32(smem);
    const int tid = threadIdx.x;
    const int wid = tid >> 5, lane = tid & 31;
    const int wm = wid >> 2, wn = wid & 3;
    const int mt = blockIdx.y, nt = blockIdx.x;

    if (tid == 0) {
        #pragma unroll
        for (int s = 0; s < 3; s++) {
            MBAR_INIT(sb + BAR_OFF + s * 8, 1);
            MBAR_INIT(sb + BAR_OFF + 24 + s * 8, 256);
        }
        asm volatile("fence.proxy.async.shared::cta;" ::: "memory");
    }
    __syncthreads();

    const size_t ablk = (size_t)mt * nkt;
    const size_t bblk = (size_t)nt * nkt;
    if (tid == 0) {
        #pragma unroll
        for (int c = 0; c < 3; c++) {
            const uint32_t st = sb + c * STG_BYTES;
            const uint32_t fb = sb + BAR_OFF + c * 8;
            MBAR_EXPECT_TX(fb, STG_BYTES);
            bulk_g2s(st,         (const char*)Ahi + (ablk + c) * 16384ull, 16384, fb);
            bulk_g2s(st + 16384, (const char*)Alo + (ablk + c) * 16384ull, 16384, fb);
            bulk_g2s(st + 32768, (const char*)Bhi + (bblk + c) * 16384ull, 16384, fb);
            bulk_g2s(st + 49152, (const char*)Blo + (bblk + c) * 16384ull, 16384, fb);
        }
    }

    const int a_row = wm * 64 + (lane & 15);
    const int a_kg  = (lane >> 4) * 16;
    const int b_row = wn * 32 + ((lane >> 4) * 8) + (lane & 7);
    const int b_kg  = ((lane >> 3) & 1) * 16;

    float acc[4][4][4];
    #pragma unroll
    for (int i = 0; i < 4; i++)
        #pragma unroll
        for (int j = 0; j < 4; j++)
            #pragma unroll
            for (int q = 0; q < 4; q++) acc[i][j][q] = 0.0f;

    for (int c = 0; c < nkt; c++) {
        const int s = c - (c / 3) * 3;
        const uint32_t ph = (uint32_t)((c / 3) & 1);
        MBAR_WAIT(sb + BAR_OFF + s * 8, ph);
        const uint32_t aH = sb + s * STG_BYTES;
        const uint32_t aL = aH + 16384;
        const uint32_t bH = aH + 32768;
        const uint32_t bL = aH + 49152;

        #pragma unroll
        for (int k16 = 0; k16 < 4; k16++) {
            const int kb = k16 * 32;
            uint32_t ahi[4][4], alo[4][4], bhi[2][4], blo[2][4];
            #pragma unroll
            for (int m4 = 0; m4 < 4; m4++) {
                const uint32_t off = sw128((uint32_t)((a_row + m4 * 16) * 128 + a_kg + kb));
                LDSM_X4(ahi[m4][0], ahi[m4][1], ahi[m4][2], ahi[m4][3], aH + off);
                LDSM_X4(alo[m4][0], alo[m4][1], alo[m4][2], alo[m4][3], aL + off);
            }
            #pragma unroll
            for (int n2 = 0; n2 < 2; n2++) {
                const uint32_t off = sw128((uint32_t)((b_row + n2 * 16) * 128 + b_kg + kb));
                LDSM_X4(bhi[n2][0], bhi[n2][1], bhi[n2][2], bhi[n2][3], bH + off);
                LDSM_X4(blo[n2][0], blo[n2][1], blo[n2][2], blo[n2][3], bL + off);
            }
            #pragma unroll
            for (int m4 = 0; m4 < 4; m4++)
                #pragma unroll
                for (int n8 = 0; n8 < 4; n8++) {
                    const int n2 = n8 >> 1, sel = (n8 & 1) * 2;
                    mma_bf16(acc[m4][n8], ahi[m4][0], ahi[m4][1], ahi[m4][2], ahi[m4][3],
                             bhi[n2][sel], bhi[n2][sel + 1]);
                    mma_bf16(acc[m4][n8], ahi[m4][0], ahi[m4][1], ahi[m4][2], ahi[m4][3],
                             blo[n2][sel], blo[n2][sel + 1]);
                    mma_bf16(acc[m4][n8], alo[m4][0], alo[m4][1], alo[m4][2], alo[m4][3],
                             bhi[n2][sel], bhi[n2][sel + 1]);
                }
        }
        MBAR_ARRIVE(sb + BAR_OFF + 24 + s * 8);
        if (tid == 0 && c + 3 < nkt) {
            MBAR_WAIT(sb + BAR_OFF + 24 + s * 8, ph);
            const uint32_t st = sb + s * STG_BYTES;
            const uint32_t fb = sb + BAR_OFF + s * 8;
            MBAR_EXPECT_TX(fb, STG_BYTES);
            bulk_g2s(st,         (const char*)Ahi + (ablk + c + 3) * 16384ull, 16384, fb);
            bulk_g2s(st + 16384, (const char*)Alo + (ablk + c + 3) * 16384ull, 16384, fb);
            bulk_g2s(st + 32768, (const char*)Bhi + (bblk + c + 3) * 16384ull, 16384, fb);
            bulk_g2s(st + 49152, (const char*)Blo + (bblk + c + 3) * 16384ull, 16384, fb);
        }
    }

    const int g = lane >> 2, tig = lane & 3;
    if (PACK) {
        // packed hi/lo block-image output
        const int nktout = N >> 6;
        const int ktout = nt * 2 + (wn >> 1);
        const size_t blkb = ((size_t)mt * nktout + ktout) * 16384ull;
        #pragma unroll
        for (int n8 = 0; n8 < 4; n8++) {
            const int colc = (wn & 1) * 32 + n8 * 8 + tig * 2;
            float2 bv = *(const float2*)&bias[(ktout << 6) + colc];
            #pragma unroll
            for (int m4 = 0; m4 < 4; m4++) {
                float v0 = acc[m4][n8][0] + bv.x;
                float v1 = acc[m4][n8][1] + bv.y;
                float v2 = acc[m4][n8][2] + bv.x;
                float v3 = acc[m4][n8][3] + bv.y;
                if (RELU) {
                    v0 = fmaxf(v0, 0.f); v1 = fmaxf(v1, 0.f);
                    v2 = fmaxf(v2, 0.f); v3 = fmaxf(v3, 0.f);
                }
                const int r0 = wm * 64 + m4 * 16 + g;
                __nv_bfloat16 h0 = __float2bfloat16(v0), h1 = __float2bfloat16(v1);
                __nv_bfloat16 h2 = __float2bfloat16(v2), h3 = __float2bfloat16(v3);
                const uint32_t o0 = sw128((uint32_t)(r0 * 128 + colc * 2));
                const uint32_t o1 = sw128((uint32_t)((r0 + 8) * 128 + colc * 2));
                *(uint32_t*)((char*)Chi + blkb + o0) = pack2(h0, h1);
                *(uint32_t*)((char*)Chi + blkb + o1) = pack2(h2, h3);
                *(uint32_t*)((char*)Clo + blkb + o0) =
                    pack2(__float2bfloat16(v0 - __bfloat162float(h0)),
                          __float2bfloat16(v1 - __bfloat162float(h1)));
                *(uint32_t*)((char*)Clo + blkb + o1) =
                    pack2(__float2bfloat16(v2 - __bfloat162float(h2)),
                          __float2bfloat16(v3 - __bfloat162float(h3)));
            }
        }
    } else {
        const int row_base = mt * 128 + wm * 64;
        const int col_base = nt * 128 + wn * 32;
        #pragma unroll
        for (int n8 = 0; n8 < 4; n8++) {
            const int col = col_base + n8 * 8 + tig * 2;
            float2 bv = *(const float2*)&bias[col];
            #pragma unroll
            for (int m4 = 0; m4 < 4; m4++) {
                const size_t r0 = (size_t)(row_base + m4 * 16 + g);
                float2 v0, v1;
                v0.x = acc[m4][n8][0] + bv.x;
                v0.y = acc[m4][n8][1] + bv.y;
                v1.x = acc[m4][n8][2] + bv.x;
                v1.y = acc[m4][n8][3] + bv.y;
                if (RELU) {
                    v0.x = fmaxf(v0.x, 0.f); v0.y = fmaxf(v0.y, 0.f);
                    v1.x = fmaxf(v1.x, 0.f); v1.y = fmaxf(v1.y, 0.f);
                }
                *(float2*)&C[r0 * N + col] = v0;
                *(float2*)&C[(r0 + 8) * N + col] = v1;
            }
        }
    }
}

// ================= tensor-core flash attention ==============================
// grid (8 qtiles, 16 heads, 4 batch), 256 threads (8 warps x 16 q-rows).
// kv tiles of 128, 2-stage pipeline. 3-term bf16 compensation on S and PV.
#define AT_QOFF 0
#define AT_SOFF 32768
#define AT_STG  65536
#define AT_BAR  (AT_SOFF + 2 * AT_STG)     // 163840
#define SMEM_ATT (AT_BAR + 64)

__global__ void __launch_bounds__(256, 1) attn_tc_kernel(
    const __nv_bfloat16* __restrict__ qhi, const __nv_bfloat16* __restrict__ qlo,
    const __nv_bfloat16* __restrict__ khi, const __nv_bfloat16* __restrict__ klo,
    const __nv_bfloat16* __restrict__ vhi, const __nv_bfloat16* __restrict__ vlo,
    __nv_bfloat16* __restrict__ ohi, __nv_bfloat16* __restrict__ olo)
{
    extern __shared__ __align__(1024) char smem[];
    const uint32_t sb = smem_u32(smem);
    const int tid = threadIdx.x;
    const int wid = tid >> 5, lane = tid & 31;
    const int qt = blockIdx.x, h = blockIdx.y, b = blockIdx.z;
    const int mtg = b * 8 + qt;

    if (tid == 0) {
        MBAR_INIT(sb + AT_BAR + 0, 1);       // q full
        MBAR_INIT(sb + AT_BAR + 8, 1);       // s0 full
        MBAR_INIT(sb + AT_BAR + 16, 1);      // s1 full
        MBAR_INIT(sb + AT_BAR + 24, 256);    // s0 empty
        MBAR_INIT(sb + AT_BAR + 32, 256);    // s1 empty
        asm volatile("fence.proxy.async.shared::cta;" ::: "memory");
    }
    __syncthreads();

    const size_t qblk = ((size_t)mtg * 16 + h) * 16384ull;
    if (tid == 0) {
        MBAR_EXPECT_TX(sb + AT_BAR + 0, 32768);
        bulk_g2s(sb + AT_QOFF,         (const char*)qhi + qblk, 16384, sb + AT_BAR + 0);
        bulk_g2s(sb + AT_QOFF + 16384, (const char*)qlo + qblk, 16384, sb + AT_BAR + 0);
        #pragma unroll
        for (int s = 0; s < 2; s++) {
            const size_t kb = ((size_t)(b * 8 + s) * 16 + h) * 16384ull;
            const uint32_t st = sb + AT_SOFF + s * AT_STG;
            const uint32_t fb = sb + AT_BAR + 8 + s * 8;
            MBAR_EXPECT_TX(fb, AT_STG);
            bulk_g2s(st,         (const char*)khi + kb, 16384, fb);
            bulk_g2s(st + 16384, (const char*)klo + kb, 16384, fb);
            bulk_g2s(st + 32768, (const char*)vhi + kb, 16384, fb);
            bulk_g2s(st + 49152, (const char*)vlo + kb, 16384, fb);
        }
    }

    // load Q fragments (per warp: rows wid*16..+15, K depth 64 = 4 k16)
    MBAR_WAIT(sb + AT_BAR + 0, 0);
    uint32_t qh[4][4], ql[4][4];
    {
        const int ar = wid * 16 + (lane & 15);
        const int akg = (lane >> 4) * 16;
        #pragma unroll
        for (int k16 = 0; k16 < 4; k16++) {
            const uint32_t off = sw128((uint32_t)(ar * 128 + akg + k16 * 32));
            LDSM_X4(qh[k16][0], qh[k16][1], qh[k16][2], qh[k16][3], sb + AT_QOFF + off);
            LDSM_X4(ql[k16][0], ql[k16][1], ql[k16][2], ql[k16][3], sb + AT_QOFF + 16384 + off);
        }
    }

    float m0 = -1e30f, m1 = -1e30f, l0 = 0.f, l1 = 0.f;
    float Oa[8][4];
    #pragma unroll
    for (int d = 0; d < 8; d++)
        #pragma unroll
        for (int q = 0; q < 4; q++) Oa[d][q] = 0.f;

    const int s_brow = ((lane >> 4) * 8) + (lane & 7);
    const int s_bkg  = ((lane >> 3) & 1) * 16;
    const int v_row  = lane & 15;
    const int v_col  = (lane >> 4) * 16;

    for (int kt = 0; kt < 8; kt++) {
        const int s = kt & 1;
        const uint32_t ph = (uint32_t)((kt >> 1) & 1);
        MBAR_WAIT(sb + AT_BAR + 8 + s * 8, ph);
        const uint32_t kH = sb + AT_SOFF + s * AT_STG;
        const uint32_t kL = kH + 16384;
        const uint32_t vH = kH + 32768;
        const uint32_t vL = kH + 49152;

        // ---- S = Q K^T (3-term), 16 n8 blocks of kv ----
        float S[16][4];
        #pragma unroll
        for (int j = 0; j < 8; j++) {        // n16 groups
            #pragma unroll
            for (int q = 0; q < 4; q++) { S[2 * j][q] = 0.f; S[2 * j + 1][q] = 0.f; }
            #pragma unroll
            for (int k16 = 0; k16 < 4; k16++) {
                const uint32_t off = sw128((uint32_t)((j * 16 + s_brow) * 128 + s_bkg + k16 * 32));
                uint32_t bh[4], bl[4];
                LDSM_X4(bh[0], bh[1], bh[2], bh[3], kH + off);
                LDSM_X4(bl[0], bl[1], bl[2], bl[3], kL + off);
                mma_bf16(S[2 * j],     qh[k16][0], qh[k16][1], qh[k16][2], qh[k16][3], bh[0], bh[1]);
                mma_bf16(S[2 * j],     qh[k16][0], qh[k16][1], qh[k16][2], qh[k16][3], bl[0], bl[1]);
                mma_bf16(S[2 * j],     ql[k16][0], ql[k16][1], ql[k16][2], ql[k16][3], bh[0], bh[1]);
                mma_bf16(S[2 * j + 1], qh[k16][0], qh[k16][1], qh[k16][2], qh[k16][3], bh[2], bh[3]);
                mma_bf16(S[2 * j + 1], qh[k16][0], qh[k16][1], qh[k16][2], qh[k16][3], bl[2], bl[3]);
                mma_bf16(S[2 * j + 1], ql[k16][0], ql[k16][1], ql[k16][2], ql[k16][3], bh[2], bh[3]);
            }
        }

        // ---- online softmax (rows g=lane>>2 and g+8) ----
        float tmx0 = -1e30f, tmx1 = -1e30f;
        #pragma unroll
        for (int j = 0; j < 16; j++) {
            S[j][0] *= SCALE_; S[j][1] *= SCALE_; S[j][2] *= SCALE_; S[j][3] *= SCALE_;
            tmx0 = fmaxf(tmx0, fmaxf(S[j][0], S[j][1]));
            tmx1 = fmaxf(tmx1, fmaxf(S[j][2], S[j][3]));
        }
        tmx0 = fmaxf(tmx0, __shfl_xor_sync(0xffffffffu, tmx0, 1));
        tmx0 = fmaxf(tmx0, __shfl_xor_sync(0xffffffffu, tmx0, 2));
        tmx1 = fmaxf(tmx1, __shfl_xor_sync(0xffffffffu, tmx1, 1));
        tmx1 = fmaxf(tmx1, __shfl_xor_sync(0xffffffffu, tmx1, 2));
        const float nm0 = fmaxf(m0, tmx0), nm1 = fmaxf(m1, tmx1);
        const float a0 = __expf(m0 - nm0), a1 = __expf(m1 - nm1);
        m0 = nm0; m1 = nm1;
        float rs0 = 0.f, rs1 = 0.f;
        #pragma unroll
        for (int j = 0; j < 16; j++) {
            S[j][0] = __expf(S[j][0] - nm0);
            S[j][1] = __expf(S[j][1] - nm0);
            S[j][2] = __expf(S[j][2] - nm1);
            S[j][3] = __expf(S[j][3] - nm1);
            rs0 += S[j][0] + S[j][1];
            rs1 += S[j][2] + S[j][3];
        }
        rs0 += __shfl_xor_sync(0xffffffffu, rs0, 1);
        rs0 += __shfl_xor_sync(0xffffffffu, rs0, 2);
        rs1 += __shfl_xor_sync(0xffffffffu, rs1, 1);
        rs1 += __shfl_xor_sync(0xffffffffu, rs1, 2);
        l0 = l0 * a0 + rs0;
        l1 = l1 * a1 + rs1;
        #pragma unroll
        for (int d = 0; d < 8; d++) {
            Oa[d][0] *= a0; Oa[d][1] *= a0; Oa[d][2] *= a1; Oa[d][3] *= a1;
        }

        // ---- O += P V (3-term). jj = kv k16 group ----
        #pragma unroll
        for (int jj = 0; jj < 8; jj++) {
            // P fragments (A operand) from S fragments
            __nv_bfloat16 h0 = __float2bfloat16(S[2 * jj][0]);
            __nv_bfloat16 h1 = __float2bfloat16(S[2 * jj][1]);
            __nv_bfloat16 h2 = __float2bfloat16(S[2 * jj][2]);
            __nv_bfloat16 h3 = __float2bfloat16(S[2 * jj][3]);
            __nv_bfloat16 h4 = __float2bfloat16(S[2 * jj + 1][0]);
            __nv_bfloat16 h5 = __float2bfloat16(S[2 * jj + 1][1]);
            __nv_bfloat16 h6 = __float2bfloat16(S[2 * jj + 1][2]);
            __nv_bfloat16 h7 = __float2bfloat16(S[2 * jj + 1][3]);
            uint32_t pa0 = pack2(h0, h1), pa1 = pack2(h2, h3);
            uint32_t pa2 = pack2(h4, h5), pa3 = pack2(h6, h7);
            uint32_t la0 = pack2(__float2bfloat16(S[2 * jj][0] - __bfloat162float(h0)),
                                 __float2bfloat16(S[2 * jj][1] - __bfloat162float(h1)));
            uint32_t la1 = pack2(__float2bfloat16(S[2 * jj][2] - __bfloat162float(h2)),
                                 __float2bfloat16(S[2 * jj][3] - __bfloat162float(h3)));
            uint32_t la2 = pack2(__float2bfloat16(S[2 * jj + 1][0] - __bfloat162float(h4)),
                                 __float2bfloat16(S[2 * jj + 1][1] - __bfloat162float(h5)));
            uint32_t la3 = pack2(__float2bfloat16(S[2 * jj + 1][2] - __bfloat162float(h6)),
                                 __float2bfloat16(S[2 * jj + 1][3] - __bfloat162float(h7)));
            #pragma unroll
            for (int dp = 0; dp < 4; dp++) {
                const uint32_t off = sw128((uint32_t)((jj * 16 + v_row) * 128 + dp * 32 + v_col));
                uint32_t bh[4], bl[4];
                LDSM_X4_T(bh[0], bh[1], bh[2], bh[3], vH + off);
                LDSM_X4_T(bl[0], bl[1], bl[2], bl[3], vL + off);
                mma_bf16(Oa[dp * 2],     pa0, pa1, pa2, pa3, bh[0], bh[1]);
                mma_bf16(Oa[dp * 2],     pa0, pa1, pa2, pa3, bl[0], bl[1]);
                mma_bf16(Oa[dp * 2],     la0, la1, la2, la3, bh[0], bh[1]);
                mma_bf16(Oa[dp * 2 + 1], pa0, pa1, pa2, pa3, bh[2], bh[3]);
                mma_bf16(Oa[dp * 2 + 1], pa0, pa1, pa2, pa3, bl[2], bl[3]);
                mma_bf16(Oa[dp * 2 + 1], la0, la1, la2, la3, bh[2], bh[3]);
            }
        }

        MBAR_ARRIVE(sb + AT_BAR + 24 + s * 8);
        if (tid == 0 && kt + 2 < 8) {
            MBAR_WAIT(sb + AT_BAR + 24 + s * 8, ph);
            const size_t kb = ((size_t)(b * 8 + kt + 2) * 16 + h) * 16384ull;
            const uint32_t st = sb + AT_SOFF + s * AT_STG;
            const uint32_t fb = sb + AT_BAR + 8 + s * 8;
            MBAR_EXPECT_TX(fb, AT_STG);
            bulk_g2s(st,         (const char*)khi + kb, 16384, fb);
            bulk_g2s(st + 16384, (const char*)klo + kb, 16384, fb);
            bulk_g2s(st + 32768, (const char*)vhi + kb, 16384, fb);
            bulk_g2s(st + 49152, (const char*)vlo + kb, 16384, fb);
        }
    }

    // ---- finalize + packed store to o block (mtg, h) ----
    const float inv0 = 1.0f / l0, inv1 = 1.0f / l1;
    const int g = lane >> 2, tig = lane & 3;
    const size_t oblk = ((size_t)mtg * 16 + h) * 16384ull;
    #pragma unroll
    for (int d = 0; d < 8; d++) {
        const int col = d * 8 + tig * 2;
        const int r0 = wid * 16 + g;
        float v0 = Oa[d][0] * inv0, v1 = Oa[d][1] * inv0;
        float v2 = Oa[d][2] * inv1, v3 = Oa[d][3] * inv1;
        __nv_bfloat16 h0 = __float2bfloat16(v0), h1 = __float2bfloat16(v1);
        __nv_bfloat16 h2 = __float2bfloat16(v2), h3 = __float2bfloat16(v3);
        const uint32_t o0 = sw128((uint32_t)(r0 * 128 + col * 2));
        const uint32_t o1 = sw128((uint32_t)((r0 + 8) * 128 + col * 2));
        *(uint32_t*)((char*)ohi + oblk + o0) = pack2(h0, h1);
        *(uint32_t*)((char*)ohi + oblk + o1) = pack2(h2, h3);
        *(uint32_t*)((char*)olo + oblk + o0) =
            pack2(__float2bfloat16(v0 - __bfloat162float(h0)),
                  __float2bfloat16(v1 - __bfloat162float(h1)));
        *(uint32_t*)((char*)olo + oblk + o1) =
            pack2(__float2bfloat16(v2 - __bfloat162float(h2)),
                  __float2bfloat16(v3 - __bfloat162float(h3)));
    }
}

// ================= fused residual add + LayerNorm ===========================
template <int PACK>
__global__ void __launch_bounds__(256) add_ln_kernel(
    const float* __restrict__ a, const float* __restrict__ b,
    const float* __restrict__ g, const float* __restrict__ be,
    float* __restrict__ out, __nv_bfloat16* __restrict__ xhi,
    __nv_bfloat16* __restrict__ xlo)
{
    __shared__ float red_s[8];
    __shared__ float red_q[8];
    const int row = blockIdx.x;
    const int tid = threadIdx.x;
    const float4* a4 = (const float4*)(a + (size_t)row * DD);
    const float4* b4 = (const float4*)(b + (size_t)row * DD);

    float4 xa = a4[tid];
    float4 xb = b4[tid];
    float4 x;
    x.x = xa.x + xb.x; x.y = xa.y + xb.y;
    x.z = xa.z + xb.z; x.w = xa.w + xb.w;

    float s  = x.x + x.y + x.z + x.w;
    float ss = x.x * x.x + x.y * x.y + x.z * x.z + x.w * x.w;
    #pragma unroll
    for (int off = 16; off >= 1; off >>= 1) {
        s  += __shfl_xor_sync(0xffffffffu, s, off);
        ss += __shfl_xor_sync(0xffffffffu, ss, off);
    }
    const int wid = tid >> 5;
    if ((tid & 31) == 0) { red_s[wid] = s; red_q[wid] = ss; }
    __syncthreads();
    float tot = 0.f, tot2 = 0.f;
    #pragma unroll
    for (int w = 0; w < 8; w++) { tot += red_s[w]; tot2 += red_q[w]; }

    const float mu = tot * (1.0f / DD);
    const float var = tot2 * (1.0f / DD) - mu * mu;
    const float rstd = rsqrtf(var + LN_EPS);

    float4 gg = ((const float4*)g)[tid];
    float4 bb = ((const float4*)be)[tid];
    float4 r;
    r.x = (x.x - mu) * rstd * gg.x + bb.x;
    r.y = (x.y - mu) * rstd * gg.y + bb.y;
    r.z = (x.z - mu) * rstd * gg.z + bb.z;
    r.w = (x.w - mu) * rstd * gg.w + bb.w;
    ((float4*)(out + (size_t)row * DD))[tid] = r;

    if (PACK) {
        const int mt = row >> 7, rowib = row & 127;
        const int kt = (tid * 4) >> 6, colc = (tid * 4) & 63;
        const size_t blk = ((size_t)mt * 16 + kt) * 16384ull;
        const uint32_t base = sw128((uint32_t)(rowib * 128 + colc * 2));
        __nv_bfloat16 h0 = __float2bfloat16(r.x), h1 = __float2bfloat16(r.y);
        __nv_bfloat16 h2 = __float2bfloat16(r.z), h3 = __float2bfloat16(r.w);
        *(uint32_t*)((char*)xhi + blk + base)     = pack2(h0, h1);
        *(uint32_t*)((char*)xhi + blk + base + 4) = pack2(h2, h3);
        *(uint32_t*)((char*)xlo + blk + base) =
            pack2(__float2bfloat16(r.x - __bfloat162float(h0)),
                  __float2bfloat16(r.y - __bfloat162float(h1)));
        *(uint32_t*)((char*)xlo + blk + base + 4) =
            pack2(__float2bfloat16(r.z - __bfloat162float(h2)),
                  __float2bfloat16(r.w - __bfloat162float(h3)));
    }
}

// ================= launcher ==================================================
extern "C" void kernel_launch(void* const* d_in, const int* in_sizes, int n_in,
                              void* d_out, int out_size)
{
    const float* Q   = (const float*)d_in[0];
    const float* K   = (const float*)d_in[1];
    const float* Wq  = (const float*)d_in[2];
    const float* bq  = (const float*)d_in[3];
    const float* Wk  = (const float*)d_in[4];
    const float* bk  = (const float*)d_in[5];
    const float* Wv  = (const float*)d_in[6];
    const float* bv  = (const float*)d_in[7];
    const float* Wo  = (const float*)d_in[8];
    const float* bo  = (const float*)d_in[9];
    const float* W1  = (const float*)d_in[10];
    const float* b1  = (const float*)d_in[11];
    const float* W2  = (const float*)d_in[12];
    const float* b2  = (const float*)d_in[13];
    const float* g0  = (const float*)d_in[14];
    const float* be0 = (const float*)d_in[15];
    const float* g1  = (const float*)d_in[16];
    const float* be1 = (const float*)d_in[17];
    float* out = (float*)d_out;

    float* F; __nv_bfloat16* P;
    cudaGetSymbolAddress((void**)&F, g_f32);
    cudaGetSymbolAddress((void**)&P, g_bf);

    static int attr_set = 0;
    if (!attr_set) {
        cudaFuncSetAttribute(tcmm_kernel<0, 0>, cudaFuncAttributeMaxDynamicSharedMemorySize, SMEM_GEMM);
        cudaFuncSetAttribute(tcmm_kernel<0, 1>, cudaFuncAttributeMaxDynamicSharedMemorySize, SMEM_GEMM);
        cudaFuncSetAttribute(tcmm_kernel<1, 1>, cudaFuncAttributeMaxDynamicSharedMemorySize, SMEM_GEMM);
        cudaFuncSetAttribute(attn_tc_kernel, cudaFuncAttributeMaxDynamicSharedMemorySize, SMEM_ATT);
        attr_set = 1;
    }

    // ---- pack weights ----
    pack_w_kernel<<<dim3(16, 8),  256>>>(Wq, P + O_WQ_HI, P + O_WQ_LO, 16, DD);
    pack_w_kernel<<<dim3(16, 8),  256>>>(Wk, P + O_WK_HI, P + O_WK_LO, 16, DD);
    pack_w_kernel<<<dim3(16, 8),  256>>>(Wv, P + O_WV_HI, P + O_WV_LO, 16, DD);
    pack_w_kernel<<<dim3(16, 8),  256>>>(Wo, P + O_WO_HI, P + O_WO_LO, 16, DD);
    pack_w_kernel<<<dim3(16, 32), 256>>>(W1, P + O_W1_HI, P + O_W1_LO, 16, DFF_);
    pack_w_kernel<<<dim3(64, 8),  256>>>(W2, P + O_W2_HI, P + O_W2_LO, 64, DD);

    // ---- pack harness inputs ----
    pack_a_kernel<<<dim3(16, 32), 256>>>(Q, P + O_PQ_HI, P + O_PQ_LO, 16, DD);
    pack_a_kernel<<<dim3(16, 32), 256>>>(K, P + O_PK_HI, P + O_PK_LO, 16, DD);

    // ---- QKV projections (packed outputs) ----
    tcmm_kernel<0, 1><<<dim3(8, 32), 256, SMEM_GEMM>>>(
        P + O_PQ_HI, P + O_PQ_LO, P + O_WQ_HI, P + O_WQ_LO, bq,
        nullptr, P + O_QP_HI, P + O_QP_LO, 16, DD);
    tcmm_kernel<0, 1><<<dim3(8, 32), 256, SMEM_GEMM>>>(
        P + O_PK_HI, P + O_PK_LO, P + O_WK_HI, P + O_WK_LO, bk,
        nullptr, P + O_KP_HI, P + O_KP_LO, 16, DD);
    tcmm_kernel<0, 1><<<dim3(8, 32), 256, SMEM_GEMM>>>(
        P + O_PK_HI, P + O_PK_LO, P + O_WV_HI, P + O_WV_LO, bv,
        nullptr, P + O_VP_HI, P + O_VP_LO, 16, DD);

    // ---- attention (tensor cores, packed o output) ----
    attn_tc_kernel<<<dim3(8, HH, BB), 256, SMEM_ATT>>>(
        P + O_QP_HI, P + O_QP_LO, P + O_KP_HI, P + O_KP_LO,
        P + O_VP_HI, P + O_VP_LO, P + O_OP_HI, P + O_OP_LO);

    // ---- output projection (fp32 out) + residual/LN0 (packed x) ----
    tcmm_kernel<0, 0><<<dim3(8, 32), 256, SMEM_GEMM>>>(
        P + O_OP_HI, P + O_OP_LO, P + O_WO_HI, P + O_WO_LO, bo,
        F + OF_T, nullptr, nullptr, 16, DD);
    add_ln_kernel<1><<<MR, 256>>>(Q, F + OF_T, g0, be0, F + OF_X,
                                  P + O_X_HI, P + O_X_LO);

    // ---- FFN ----
    tcmm_kernel<1, 1><<<dim3(32, 32), 256, SMEM_GEMM>>>(
        P + O_X_HI, P + O_X_LO, P + O_W1_HI, P + O_W1_LO, b1,
        nullptr, P + O_H_HI, P + O_H_LO, 16, DFF_);
    tcmm_kernel<0, 0><<<dim3(8, 32), 256, SMEM_GEMM>>>(
        P + O_H_HI, P + O_H_LO, P + O_W2_HI, P + O_W2_LO, b2,
        F + OF_T, nullptr, nullptr, 64, DD);

    // ---- residual + LN1 -> output ----
    add_ln_kernel<0><<<MR, 256>>>(F + OF_X, F + OF_T, g1, be1, out, nullptr, nullptr);
}